// round 12
// baseline (speedup 1.0000x reference)
#include <cuda_runtime.h>
#include <math.h>

#define BB 512
#define TT 1024
#define EE 64
#define HH 32
#define PP 720

#define N_SCAN_BLK 64
#define N_Z0_BLK   8192
#define N_MLP_BLK  2880   // 45 p-chunks x 64 b-groups
#define N_PCHUNK   45

typedef unsigned long long u64;

// ---------------- scratch (device globals: no allocation allowed) ----------
__device__ float g_z0[(size_t)TT * BB * HH];   // [t][b][h]
__device__ float g_ts1[(size_t)PP * BB * HH];  // [p][b][h]
// sync flags (zero-init at module load; every launch returns them to zero)
__device__ int g_zflag[BB * 16];   // z0 chunk (b, t/64) ready
__device__ int g_pc[N_PCHUNK];    // transition p-chunk arrivals (target 512)
__device__ int g_cons[N_PCHUNK];  // mlp consumer count (target 64 -> reset)

#define WBAR() asm volatile("" ::: "memory")

// ---------------- packed fp32x2 helpers (Blackwell FFMA2) ------------------
__device__ __forceinline__ u64 pk(float a, float b) {
    u64 r; asm("mov.b64 %0, {%1,%2};" : "=l"(r) : "f"(a), "f"(b)); return r;
}
__device__ __forceinline__ float2 upk(u64 v) {
    float2 r; asm("mov.b64 {%0,%1}, %2;" : "=f"(r.x), "=f"(r.y) : "l"(v)); return r;
}
__device__ __forceinline__ u64 fma2(u64 a, u64 b, u64 c) {
    u64 d; asm("fma.rn.f32x2 %0, %1, %2, %3;" : "=l"(d) : "l"(a), "l"(b), "l"(c)); return d;
}
__device__ __forceinline__ u64 add2(u64 a, u64 b) {
    u64 d; asm("add.rn.f32x2 %0, %1, %2;" : "=l"(d) : "l"(a), "l"(b)); return d;
}

__device__ __forceinline__ float ftanh(float x) {
    float e;
    asm("ex2.approx.f32 %0, %1;" : "=f"(e) : "f"(x * 2.885390081777927f));
    return 1.0f - __fdividef(2.0f, e + 1.0f);
}

// exact-GELU via Abramowitz-Stegun 7.1.26 erf (abs err <= 1.5e-7).
__device__ __forceinline__ float gelu(float x) {
    const float u = x * 0.70710678118654752f;
    const float au = fabsf(u);
    const float t = __fdividef(1.0f, fmaf(0.3275911f, au, 1.0f));
    const float e = __expf(-u * u);
    float p = fmaf(t, 1.061405429f, -1.453152027f);
    p = fmaf(t, p, 1.421413741f);
    p = fmaf(t, p, -0.284496736f);
    p = fmaf(t, p, 0.254829592f);
    const float erf_abs = fmaf(-p * t, e, 1.0f);
    const float er = copysignf(erf_abs, u);
    return 0.5f * x * (1.0f + er);
}

// ---------------- scan math (R8/R9-verified) --------------------------------
__device__ __forceinline__ void scan_dots(const float* __restrict__ shArow,
                                          const float* __restrict__ shBrow,
                                          const u64* w0p, const u64* wi1p,
                                          const u64* wh1p,
                                          float zin, float bias1,
                                          float& o0, float& o12) {
    const u64 ZZ = pk(0.0f, 0.0f);
    u64 m0a = pk(zin, 0.0f), m0b = ZZ, m0c = ZZ, m0d = ZZ;
    u64 m1a = pk(bias1, 0.0f), m1b = ZZ, m1c = ZZ, m1d = ZZ;
    u64 m2a = ZZ, m2b = ZZ, m2c = ZZ, m2d = ZZ;
#pragma unroll
    for (int q = 0; q < 4; q++) {
        ulonglong2 a0 = *(const ulonglong2*)&shArow[8 * q];
        ulonglong2 a1 = *(const ulonglong2*)&shArow[8 * q + 4];
        ulonglong2 c0 = *(const ulonglong2*)&shBrow[8 * q];
        ulonglong2 c1 = *(const ulonglong2*)&shBrow[8 * q + 4];
        m0a = fma2(a0.x, w0p[4 * q + 0], m0a);
        m0b = fma2(a0.y, w0p[4 * q + 1], m0b);
        m0c = fma2(a1.x, w0p[4 * q + 2], m0c);
        m0d = fma2(a1.y, w0p[4 * q + 3], m0d);
        m1a = fma2(a0.x, wi1p[4 * q + 0], m1a);
        m1b = fma2(a0.y, wi1p[4 * q + 1], m1b);
        m1c = fma2(a1.x, wi1p[4 * q + 2], m1c);
        m1d = fma2(a1.y, wi1p[4 * q + 3], m1d);
        m2a = fma2(c0.x, wh1p[4 * q + 0], m2a);
        m2b = fma2(c0.y, wh1p[4 * q + 1], m2b);
        m2c = fma2(c1.x, wh1p[4 * q + 2], m2c);
        m2d = fma2(c1.y, wh1p[4 * q + 3], m2d);
    }
    float2 r0 = upk(add2(add2(m0a, m0b), add2(m0c, m0d)));
    float2 r1 = upk(add2(add2(m1a, m1b), add2(m1c, m1d)));
    float2 r2 = upk(add2(add2(m2a, m2b), add2(m2c, m2d)));
    o0 = r0.x + r0.y;
    o12 = (r1.x + r1.y) + (r2.x + r2.y);
}

__device__ __forceinline__ float scan_dot1(const float* __restrict__ shArow,
                                           const float* __restrict__ shBrow,
                                           const u64* wi1p, const u64* wh1p,
                                           float bias1) {
    const u64 ZZ = pk(0.0f, 0.0f);
    u64 m1a = pk(bias1, 0.0f), m1b = ZZ, m2a = ZZ, m2b = ZZ;
#pragma unroll
    for (int q = 0; q < 8; q++) {
        ulonglong2 a = *(const ulonglong2*)&shArow[4 * q];
        ulonglong2 c = *(const ulonglong2*)&shBrow[4 * q];
        m1a = fma2(a.x, wi1p[2 * q], m1a);  m1b = fma2(a.y, wi1p[2 * q + 1], m1b);
        m2a = fma2(c.x, wh1p[2 * q], m2a);  m2b = fma2(c.y, wh1p[2 * q + 1], m2b);
    }
    float2 r1 = upk(add2(m1a, m1b));
    float2 r2 = upk(add2(m2a, m2b));
    return (r1.x + r1.y) + (r2.x + r2.y);
}

#define ASSIGN_SCAN_WEIGHTS(W0, WI1, WH1)                                      \
    _Pragma("unroll")                                                          \
    for (int i = 0; i < 8; i++) {                                              \
        float4 v0 = *(const float4*)&(W0)[lane * HH + 4 * i];                  \
        float4 v1 = *(const float4*)&(WI1)[lane * HH + 4 * i];                 \
        float4 v2 = *(const float4*)&(WH1)[lane * HH + 4 * i];                 \
        w0p[2 * i] = pk(v0.x, v0.y);  w0p[2 * i + 1] = pk(v0.z, v0.w);         \
        wi1p[2 * i] = pk(v1.x, v1.y); wi1p[2 * i + 1] = pk(v1.z, v1.w);        \
        wh1p[2 * i] = pk(v2.x, v2.y); wh1p[2 * i + 1] = pk(v2.z, v2.w);        \
    }

// wait for z0 chunk (b, c); acquire.
__device__ __forceinline__ void zwait(int b, int c) {
    if ((threadIdx.x & 31) == 0) {
        volatile int* f = &g_zflag[b * 16 + c];
        while (*f == 0) __nanosleep(64);
    }
    __syncwarp();
    __threadfence();
}

// ============================================================================
// Role A: scan (blocks 0..63, dispatched first -> resident wave 1).
// One warp per batch row, 8 warps/block. Consumes z chunks, produces ts1
// p-chunk signals for the mlp role.
// ============================================================================
__device__ void scan_role(
    float* sm, int sblk,
    const float* eWhh0, const float* eWih1, const float* eWhh1,
    const float* ebih1, const float* ebhh1,
    const float* tWhh0, const float* tbih0, const float* tbhh0,
    const float* tWih1, const float* tWhh1, const float* tbih1,
    const float* tbhh1) {
    const int lane = threadIdx.x & 31;
    const int w = threadIdx.x >> 5;           // 0..7
    const int b = sblk * 8 + w;
    const int ST = BB * HH;

    // shared layout: A[2][8][32] at sm[0..511], B[2][8][32] at sm[512..1023]
    float* sA0 = sm + w * 32;
    float* sA1 = sm + 256 + w * 32;
    float* sB0 = sm + 512 + w * 32;
    float* sB1 = sm + 768 + w * 32;

    u64 w0p[16], wi1p[16], wh1p[16];
    ASSIGN_SCAN_WEIGHTS(eWhh0, eWih1, eWhh1)
    float bias1 = ebih1[lane] + ebhh1[lane];

    sA0[lane] = 0.0f;
    sB0[lane] = 0.0f;
    WBAR();

    // ---------- phase 1: encoder ----------
    const float* zp = g_z0 + (long)b * HH + lane;
    zwait(b, 0);

    float zbuf[8];
#pragma unroll
    for (int i = 0; i < 8; i++) zbuf[i] = zp[(long)i * ST];

    float h0last = 0.0f;

    for (int t0 = 0; t0 < TT; t0 += 8) {
        if ((t0 & 63) == 0) {
            const int c = t0 >> 6;
            if (c < 15) zwait(b, c + 1);   // prefetch reads into chunk c+1
        }
        const bool pf = (t0 + 8 < TT);
#pragma unroll
        for (int u = 0; u < 8; u++) {
            const int t = t0 + u;
            float* sAc = (u & 1) ? sA1 : sA0;
            float* sAn = (u & 1) ? sA0 : sA1;
            float* sBc = (u & 1) ? sB1 : sB0;
            float* sBn = (u & 1) ? sB0 : sB1;
            const float zin = zbuf[u];
            if (pf) zbuf[u] = zp[(long)(t + 8) * ST];

            float o0, o12;
            scan_dots(sAc, sBc, w0p, wi1p, wh1p, zin, bias1, o0, o12);
            const float h0v = ftanh(o0);
            const float h1v = (t > 0) ? ftanh(o12) : 0.0f;
            sAn[lane] = h0v;
            sBn[lane] = h1v;
            h0last = h0v;
            WBAR();
        }
    }
    const float hT0 = h0last;
    const float hT1 = ftanh(scan_dot1(sA0, sB0, wi1p, wh1p, bias1));

    // reset this row's z flags for the next graph replay (all were consumed)
    if (lane < 16) g_zflag[b * 16 + lane] = 0;

    // ---------- phase 2: transition ----------
    ASSIGN_SCAN_WEIGHTS(tWhh0, tWih1, tWhh1)
    const float bias0 = tbih0[lane] + tbhh0[lane];
    bias1 = tbih1[lane] + tbhh1[lane];

    sA0[lane] = hT0;
    sB0[lane] = hT1;
    WBAR();

    float* tp = g_ts1 + (long)b * HH + lane;

    for (int p0 = 0; p0 < PP; p0 += 8) {
        // at top of block p0 (stores complete through t1[p0-2]):
        // chunk q=(p0>>4)-2 needs t1[16q+15] = t1[p0-17] <= t1[p0-2]  ✓
        if ((p0 & 15) == 0 && p0 >= 32) {
            __threadfence();
            __syncwarp();
            if (lane == 0) atomicAdd(&g_pc[(p0 >> 4) - 2], 1);
        }
#pragma unroll
        for (int u = 0; u < 8; u++) {
            const int p = p0 + u;
            float* sAc = (u & 1) ? sA1 : sA0;
            float* sAn = (u & 1) ? sA0 : sA1;
            float* sBc = (u & 1) ? sB1 : sB0;
            float* sBn = (u & 1) ? sB0 : sB1;

            float o0, o12;
            scan_dots(sAc, sBc, w0p, wi1p, wh1p, bias0, bias1, o0, o12);
            const float h0v = ftanh(o0);                 // t0[p]
            const float h1v = ftanh(o12);                // t1[p-1]
            if (p > 0) tp[(long)(p - 1) * ST] = h1v;
            sAn[lane] = h0v;
            sBn[lane] = (p > 0) ? h1v : hT1;
            WBAR();
        }
    }
    // epilogue: t1[P-1]
    tp[(long)(PP - 1) * ST] = ftanh(scan_dot1(sA0, sB0, wi1p, wh1p, bias1));
    __threadfence();
    __syncwarp();
    if (lane == 0) {
        atomicAdd(&g_pc[N_PCHUNK - 2], 1);
        atomicAdd(&g_pc[N_PCHUNK - 1], 1);
    }
}

// ============================================================================
// Role B: z0 producer (blocks 64..64+8191, chunk-major: low t first).
// R9-verified math; signals g_zflag[b][c] on completion.
// ============================================================================
__device__ void z0_role(float* sm, int idx, const float* x,
                        const float* Wih0, const float* bih0,
                        const float* bhh0) {
    float* Xs = sm;             // [64][64]  4096 floats
    float* WsT = sm + 4096;     // [64][33]  2112 floats
    float* bs = sm + 6208;      // [32]

    const int tid = threadIdx.x;
    const int b = idx & (BB - 1);
    const int c = idx >> 9;
    const long R0 = (long)b * TT + (long)c * 64;

    {
        const float4* src = (const float4*)(x + R0 * EE);
        float4* dst = (float4*)Xs;
#pragma unroll
        for (int i = 0; i < 4; i++) dst[tid + 256 * i] = src[tid + 256 * i];
    }
    for (int i4 = tid; i4 < 512; i4 += 256) {
        float4 v = ((const float4*)Wih0)[i4];
        const int h = i4 >> 4;
        const int e0 = (i4 & 15) * 4;
        WsT[(e0 + 0) * 33 + h] = v.x;
        WsT[(e0 + 1) * 33 + h] = v.y;
        WsT[(e0 + 2) * 33 + h] = v.z;
        WsT[(e0 + 3) * 33 + h] = v.w;
    }
    if (tid < HH) bs[tid] = bih0[tid] + bhh0[tid];
    __syncthreads();

    const int h = tid & 31;
    const int rbase = tid >> 5;

    u64 wp[EE / 2];
#pragma unroll
    for (int k = 0; k < EE / 2; k++)
        wp[k] = pk(WsT[(2 * k) * 33 + h], WsT[(2 * k + 1) * 33 + h]);
    const float bias = bs[h];

#pragma unroll
    for (int rr = 0; rr < 8; rr++) {
        const int r = rbase + 8 * rr;
        u64 a = pk(bias, 0.0f), bb = pk(0.0f, 0.0f);
#pragma unroll
        for (int e4 = 0; e4 < EE / 4; e4++) {
            ulonglong2 xv = *(const ulonglong2*)&Xs[r * EE + 4 * e4];
            a = fma2(xv.x, wp[2 * e4 + 0], a);
            bb = fma2(xv.y, wp[2 * e4 + 1], bb);
        }
        float2 u = upk(add2(a, bb));
        const int t = c * 64 + r;
        g_z0[((long)t * BB + b) * HH + h] = u.x + u.y;
    }

    // release: all stores visible, then set flag once
    __threadfence();
    __syncthreads();
    if (tid == 0) atomicExch(&g_zflag[b * 16 + c], 1);
}

// ============================================================================
// Role C: mlp consumer (last 2880 blocks, p-chunk-major). R9-verified math
// (128-row tile); spins on its p-chunk counter before staging ts1.
// ============================================================================
__device__ void mlp_role(float* sm, int idx, const float* W1,
                         const float* b1, const float* W2,
                         const float* b2, float* out) {
    float* Xs  = sm;                  // [128][32]
    float* W1s = sm + 4096;           // [64][36]
    float* W2s = sm + 6400;           // [64][68]
    float* Gs  = sm + 10752;          // [128][64]
    float* b1s = sm + 18944;
    float* b2s = sm + 19008;

    const int q = idx >> 6;           // p-chunk 0..44
    const int bg = idx & 63;
    const int tid = threadIdx.x;
    const int tx = tid & 15;
    const int ty = tid >> 4;
    const int p0 = q * 16;
    const int b0 = bg * 8;

    // acquire: wait until all 512 scan warps signaled this p-chunk
    if (tid == 0) {
        volatile int* f = &g_pc[q];
        while (*f < 512) __nanosleep(128);
    }
    __syncthreads();
    __threadfence();

    for (int i4 = tid; i4 < 1024; i4 += 256) {
        const int r = i4 >> 3, c4 = i4 & 7;
        const int bl = r >> 4, pl = r & 15;
        ((float4*)Xs)[i4] =
            *(const float4*)&g_ts1[((long)(p0 + pl) * BB + (b0 + bl)) * HH + 4 * c4];
    }
    for (int i4 = tid; i4 < 512; i4 += 256) {
        const int j = i4 >> 3, k4 = i4 & 7;
        ((float4*)W1s)[j * 9 + k4] = ((const float4*)W1)[i4];
    }
    for (int i4 = tid; i4 < 1024; i4 += 256) {
        const int e = i4 >> 4, j4 = i4 & 15;
        ((float4*)W2s)[e * 17 + j4] = ((const float4*)W2)[i4];
    }
    if (tid < 64) b1s[tid] = b1[tid];
    else if (tid < 128) b2s[tid - 64] = b2[tid - 64];
    __syncthreads();

    u64 acc[8][4];
#pragma unroll
    for (int i = 0; i < 8; i++)
#pragma unroll
        for (int j = 0; j < 4; j++) acc[i][j] = pk(b1s[tx + 16 * j], 0.0f);

#pragma unroll
    for (int k4 = 0; k4 < 8; k4++) {
        ulonglong2 wv[4];
#pragma unroll
        for (int j = 0; j < 4; j++)
            wv[j] = *(const ulonglong2*)&W1s[(tx + 16 * j) * 36 + 4 * k4];
#pragma unroll
        for (int i = 0; i < 8; i++) {
            ulonglong2 xv = *(const ulonglong2*)&Xs[(8 * ty + i) * 32 + 4 * k4];
#pragma unroll
            for (int j = 0; j < 4; j++) {
                acc[i][j] = fma2(xv.x, wv[j].x, acc[i][j]);
                acc[i][j] = fma2(xv.y, wv[j].y, acc[i][j]);
            }
        }
    }

#pragma unroll
    for (int i = 0; i < 8; i++) {
#pragma unroll
        for (int j = 0; j < 4; j++) {
            float2 uj = upk(acc[i][j]);
            Gs[(8 * ty + i) * 64 + tx + 16 * j] = gelu(uj.x + uj.y);
        }
    }
    __syncthreads();

#pragma unroll
    for (int i = 0; i < 8; i++)
#pragma unroll
        for (int j = 0; j < 4; j++) acc[i][j] = pk(b2s[tx + 16 * j], 0.0f);

#pragma unroll
    for (int k4 = 0; k4 < 16; k4++) {
        ulonglong2 wv[4];
#pragma unroll
        for (int j = 0; j < 4; j++)
            wv[j] = *(const ulonglong2*)&W2s[(tx + 16 * j) * 68 + 4 * k4];
#pragma unroll
        for (int i = 0; i < 8; i++) {
            ulonglong2 gv = *(const ulonglong2*)&Gs[(8 * ty + i) * 64 + 4 * k4];
#pragma unroll
            for (int j = 0; j < 4; j++) {
                acc[i][j] = fma2(gv.x, wv[j].x, acc[i][j]);
                acc[i][j] = fma2(gv.y, wv[j].y, acc[i][j]);
            }
        }
    }

    float y[8][4];
#pragma unroll
    for (int i = 0; i < 8; i++)
#pragma unroll
        for (int j = 0; j < 4; j++) {
            float2 uj = upk(acc[i][j]);
            y[i][j] = uj.x + uj.y;
        }

    const int bl = ty >> 1;
    const int plb = (ty & 1) * 8;
    float* ob = out + (long)(b0 + bl) * EE * PP + p0 + plb;
#pragma unroll
    for (int j = 0; j < 4; j++) {
        const int e = tx + 16 * j;
#pragma unroll
        for (int qq = 0; qq < 2; qq++) {
            float4 v;
            v.x = y[4 * qq + 0][j]; v.y = y[4 * qq + 1][j];
            v.z = y[4 * qq + 2][j]; v.w = y[4 * qq + 3][j];
            *(float4*)&ob[(long)e * PP + 4 * qq] = v;
        }
    }

    // consumer-side reset for next replay: 64th consumer of chunk q clears it
    __syncthreads();
    if (tid == 0) {
        const int done = atomicAdd(&g_cons[q], 1);
        if (done == 63) { g_pc[q] = 0; g_cons[q] = 0; }
    }
}

// ============================================================================
// The fused kernel: block roles by blockIdx.x.
// ============================================================================
#define FUSED_SMEM_FLOATS (4096 + 2304 + 4352 + 8192 + 128)  // mlp's (max) layout

__global__ __launch_bounds__(256, 2) void k_fused(
    const float* __restrict__ x,
    const float* __restrict__ eWih0, const float* __restrict__ ebih0,
    const float* __restrict__ ebhh0,
    const float* __restrict__ eWhh0, const float* __restrict__ eWih1,
    const float* __restrict__ eWhh1, const float* __restrict__ ebih1,
    const float* __restrict__ ebhh1,
    const float* __restrict__ tWhh0, const float* __restrict__ tbih0,
    const float* __restrict__ tbhh0, const float* __restrict__ tWih1,
    const float* __restrict__ tWhh1, const float* __restrict__ tbih1,
    const float* __restrict__ tbhh1,
    const float* __restrict__ oW1, const float* __restrict__ ob1,
    const float* __restrict__ oW2, const float* __restrict__ ob2,
    float* __restrict__ out) {
    extern __shared__ __align__(16) float sm[];
    const int bid = blockIdx.x;
    if (bid < N_SCAN_BLK) {
        scan_role(sm, bid, eWhh0, eWih1, eWhh1, ebih1, ebhh1,
                  tWhh0, tbih0, tbhh0, tWih1, tWhh1, tbih1, tbhh1);
    } else if (bid < N_SCAN_BLK + N_Z0_BLK) {
        z0_role(sm, bid - N_SCAN_BLK, x, eWih0, ebih0, ebhh0);
    } else {
        mlp_role(sm, bid - N_SCAN_BLK - N_Z0_BLK, oW1, ob1, oW2, ob2, out);
    }
}

// ============================================================================
extern "C" void kernel_launch(void* const* d_in, const int* in_sizes, int n_in,
                              void* d_out, int out_size) {
    (void)in_sizes; (void)n_in; (void)out_size;
    const float* x      = (const float*)d_in[0];
    const float* e_Wih0 = (const float*)d_in[1];
    const float* e_Whh0 = (const float*)d_in[2];
    const float* e_bih0 = (const float*)d_in[3];
    const float* e_bhh0 = (const float*)d_in[4];
    const float* e_Wih1 = (const float*)d_in[5];
    const float* e_Whh1 = (const float*)d_in[6];
    const float* e_bih1 = (const float*)d_in[7];
    const float* e_bhh1 = (const float*)d_in[8];
    // d_in[9] = t_Wih0: unused (transition input is zeros)
    const float* t_Whh0 = (const float*)d_in[10];
    const float* t_bih0 = (const float*)d_in[11];
    const float* t_bhh0 = (const float*)d_in[12];
    const float* t_Wih1 = (const float*)d_in[13];
    const float* t_Whh1 = (const float*)d_in[14];
    const float* t_bih1 = (const float*)d_in[15];
    const float* t_bhh1 = (const float*)d_in[16];
    const float* o_W1   = (const float*)d_in[17];
    const float* o_b1   = (const float*)d_in[18];
    const float* o_W2   = (const float*)d_in[19];
    const float* o_b2   = (const float*)d_in[20];
    float* out = (float*)d_out;

    cudaFuncSetAttribute(k_fused, cudaFuncAttributeMaxDynamicSharedMemorySize,
                         FUSED_SMEM_FLOATS * 4);

    const int grid = N_SCAN_BLK + N_Z0_BLK + N_MLP_BLK;
    k_fused<<<grid, 256, FUSED_SMEM_FLOATS * 4>>>(
        x, e_Wih0, e_bih0, e_bhh0,
        e_Whh0, e_Wih1, e_Whh1, e_bih1, e_bhh1,
        t_Whh0, t_bih0, t_bhh0, t_Wih1, t_Whh1, t_bih1, t_bhh1,
        o_W1, o_b1, o_W2, o_b2, out);
}

// round 13
// speedup vs baseline: 1.4025x; 1.4025x over previous
#include <cuda_runtime.h>
#include <math.h>

#define BB 512
#define TT 1024
#define EE 64
#define HH 32
#define PP 720

#define CH 16                       // steps per ring chunk
#define NRING 4                     // ring depth (chunks)
#define ENC_CHUNKS (TT / CH)        // 64
#define TRA_CHUNKS (PP / CH)        // 45

typedef unsigned long long u64;

// ---------------- scratch (device globals: no allocation allowed) ----------
__device__ float g_z0[(size_t)TT * BB * HH];   // [t][b][h]
__device__ float g_ts1[(size_t)PP * BB * HH];  // [p][b][h]

#define WBAR() asm volatile("" ::: "memory")

// ---------------- packed fp32x2 helpers (Blackwell FFMA2) ------------------
__device__ __forceinline__ u64 pk(float a, float b) {
    u64 r; asm("mov.b64 %0, {%1,%2};" : "=l"(r) : "f"(a), "f"(b)); return r;
}
__device__ __forceinline__ float2 upk(u64 v) {
    float2 r; asm("mov.b64 {%0,%1}, %2;" : "=f"(r.x), "=f"(r.y) : "l"(v)); return r;
}
__device__ __forceinline__ u64 fma2(u64 a, u64 b, u64 c) {
    u64 d; asm("fma.rn.f32x2 %0, %1, %2, %3;" : "=l"(d) : "l"(a), "l"(b), "l"(c)); return d;
}
__device__ __forceinline__ u64 add2(u64 a, u64 b) {
    u64 d; asm("add.rn.f32x2 %0, %1, %2;" : "=l"(d) : "l"(a), "l"(b)); return d;
}

// fast tanh: tanh(x) = 1 - 2/(1+exp(2x)); exact at both saturations.
__device__ __forceinline__ float ftanh(float x) {
    float e;
    asm("ex2.approx.f32 %0, %1;" : "=f"(e) : "f"(x * 2.885390081777927f));
    return 1.0f - __fdividef(2.0f, e + 1.0f);
}

// exact-GELU via Abramowitz-Stegun 7.1.26 erf (abs err <= 1.5e-7).
__device__ __forceinline__ float gelu(float x) {
    const float u = x * 0.70710678118654752f;
    const float au = fabsf(u);
    const float t = __fdividef(1.0f, fmaf(0.3275911f, au, 1.0f));
    const float e = __expf(-u * u);
    float p = fmaf(t, 1.061405429f, -1.453152027f);
    p = fmaf(t, p, 1.421413741f);
    p = fmaf(t, p, -0.284496736f);
    p = fmaf(t, p, 0.254829592f);
    const float erf_abs = fmaf(-p * t, e, 1.0f);
    const float er = copysignf(erf_abs, u);
    return 0.5f * x * (1.0f + er);
}

// dot(32-float shared vector, packed weight row) + init; 4 split chains
__device__ __forceinline__ float dot32w(const u64* wp,
                                        const float* __restrict__ sh,
                                        float init) {
    const u64 ZZ = pk(0.0f, 0.0f);
    u64 a = pk(init, 0.0f), b = ZZ, c = ZZ, d = ZZ;
#pragma unroll
    for (int q = 0; q < 4; q++) {
        ulonglong2 v0 = *(const ulonglong2*)&sh[8 * q];
        ulonglong2 v1 = *(const ulonglong2*)&sh[8 * q + 4];
        a = fma2(v0.x, wp[4 * q + 0], a);
        b = fma2(v0.y, wp[4 * q + 1], b);
        c = fma2(v1.x, wp[4 * q + 2], c);
        d = fma2(v1.y, wp[4 * q + 3], d);
    }
    float2 r = upk(add2(add2(a, b), add2(c, d)));
    return r.x + r.y;
}

#define LOAD_WROW(DST, SRC)                                                    \
    _Pragma("unroll")                                                          \
    for (int i = 0; i < 8; i++) {                                              \
        float4 v = *(const float4*)&(SRC)[lane * HH + 4 * i];                  \
        (DST)[2 * i] = pk(v.x, v.y);                                           \
        (DST)[2 * i + 1] = pk(v.z, v.w);                                       \
    }

// ============================================================================
// Kernel 1: z0 (R9-verified: 95us). Transposed weight staging, conflict-free.
// ============================================================================
__global__ __launch_bounds__(256) void k_z0(const float* __restrict__ x,
                                            const float* __restrict__ Wih0,
                                            const float* __restrict__ bih0,
                                            const float* __restrict__ bhh0) {
    __shared__ __align__(16) float Xs[64 * EE];
    __shared__ float WsT[EE * 33];
    __shared__ float bs[HH];

    const int tid = threadIdx.x;
    const long R0 = (long)blockIdx.x * 64;

    {
        const float4* src = (const float4*)(x + R0 * EE);
        float4* dst = (float4*)Xs;
#pragma unroll
        for (int i = 0; i < 4; i++) dst[tid + 256 * i] = src[tid + 256 * i];
    }
    for (int i4 = tid; i4 < 512; i4 += 256) {
        float4 v = ((const float4*)Wih0)[i4];
        const int h = i4 >> 4;
        const int e0 = (i4 & 15) * 4;
        WsT[(e0 + 0) * 33 + h] = v.x;
        WsT[(e0 + 1) * 33 + h] = v.y;
        WsT[(e0 + 2) * 33 + h] = v.z;
        WsT[(e0 + 3) * 33 + h] = v.w;
    }
    if (tid < HH) bs[tid] = bih0[tid] + bhh0[tid];
    __syncthreads();

    const int h = tid & 31;
    const int rbase = tid >> 5;

    u64 wp[EE / 2];
#pragma unroll
    for (int k = 0; k < EE / 2; k++)
        wp[k] = pk(WsT[(2 * k) * 33 + h], WsT[(2 * k + 1) * 33 + h]);
    const float bias = bs[h];

#pragma unroll
    for (int rr = 0; rr < 8; rr++) {
        const int r = rbase + 8 * rr;
        u64 a = pk(bias, 0.0f), b = pk(0.0f, 0.0f);
#pragma unroll
        for (int e4 = 0; e4 < EE / 4; e4++) {
            ulonglong2 xv = *(const ulonglong2*)&Xs[r * EE + 4 * e4];  // bcast
            a = fma2(xv.x, wp[2 * e4 + 0], a);
            b = fma2(xv.y, wp[2 * e4 + 1], b);
        }
        float2 u = upk(add2(a, b));
        const long R = R0 + r;
        const int bidx = (int)(R >> 10);
        const int t = (int)(R & 1023);
        g_z0[((long)t * BB + bidx) * HH + h] = u.x + u.y;
    }
}

// ============================================================================
// Kernel 2: scan with PRODUCER/CONSUMER warp split + chunked ring handshake.
//   warp 2r   (A): layer-0 recurrence, writes h0/t0 chunks into shared ring
//   warp 2r+1 (B): layer-1 recurrence, reads ring, writes ts1 (transition)
// Sync once per 16 steps via block-shared volatile counters (graph-safe:
// block-local, re-initialized every launch). 4 rows/block, grid 128.
// ============================================================================
__global__ __launch_bounds__(256) void k_scan2(
    const float* __restrict__ eWhh0, const float* __restrict__ eWih1,
    const float* __restrict__ eWhh1, const float* __restrict__ ebih1,
    const float* __restrict__ ebhh1,
    const float* __restrict__ tWhh0, const float* __restrict__ tbih0,
    const float* __restrict__ tbhh0, const float* __restrict__ tWih1,
    const float* __restrict__ tWhh1, const float* __restrict__ tbih1,
    const float* __restrict__ tbhh1) {
    __shared__ __align__(16) float ring[4][NRING][CH][HH];  // 32 KB
    __shared__ __align__(16) float sA[4][2][HH];
    __shared__ __align__(16) float sB[4][2][HH];
    __shared__ volatile int prod[4];
    __shared__ volatile int cons[4];

    const int tid = threadIdx.x;
    const int lane = tid & 31;
    const int w = tid >> 5;
    const int r = w >> 1;         // local row 0..3
    const int role = w & 1;       // 0 = layer-0 producer, 1 = layer-1 consumer
    const int b = blockIdx.x * 4 + r;
    const int ST = BB * HH;

    if (tid < 4) { prod[tid] = 0; cons[tid] = 0; }
    __syncthreads();

    if (role == 0) {
        // ================= producer: layer-0 chains =================
        u64 wp[16];
        LOAD_WROW(wp, eWhh0)
        sA[r][0][lane] = 0.0f;
        WBAR();

        const float* zp = g_z0 + (long)b * HH + lane;
        float zbuf[8];
#pragma unroll
        for (int i = 0; i < 8; i++) zbuf[i] = zp[(long)i * ST];

        float h = 0.0f;
        for (int k = 0; k < ENC_CHUNKS; k++) {
            if (k >= NRING) {
                while (cons[r] < k - (NRING - 1)) __nanosleep(32);
            }
            WBAR();
            float* slot = (float*)&ring[r][k & (NRING - 1)][0][0];
#pragma unroll
            for (int s = 0; s < CH; s++) {
                const int t = k * CH + s;
                const int cur = t & 1, nxt = cur ^ 1;
                const float zin = zbuf[t & 7];
                if (t + 8 < TT) zbuf[t & 7] = zp[(long)(t + 8) * ST];
                h = ftanh(dot32w(wp, sA[r][cur], zin));
                sA[r][nxt][lane] = h;
                slot[s * HH + lane] = h;
                WBAR();
            }
            __threadfence_block();
            __syncwarp();
            if (lane == 0) prod[r] = k + 1;
        }
        const float hT0 = h;

        // transition layer 0: t0[p] = tanh(bias0 + Whh0 . t0[p-1])
        LOAD_WROW(wp, tWhh0)
        const float bias0 = tbih0[lane] + tbhh0[lane];
        sA[r][0][lane] = hT0;
        WBAR();

        for (int k = 0; k < TRA_CHUNKS; k++) {
            const int gk = ENC_CHUNKS + k;
            while (cons[r] < gk - (NRING - 1)) __nanosleep(32);
            WBAR();
            float* slot = (float*)&ring[r][gk & (NRING - 1)][0][0];
#pragma unroll
            for (int s = 0; s < CH; s++) {
                const int p = k * CH + s;
                const int cur = p & 1, nxt = cur ^ 1;
                h = ftanh(dot32w(wp, sA[r][cur], bias0));
                sA[r][nxt][lane] = h;
                slot[s * HH + lane] = h;
                WBAR();
            }
            __threadfence_block();
            __syncwarp();
            if (lane == 0) prod[r] = gk + 1;
        }
    } else {
        // ================= consumer: layer-1 chains =================
        u64 wip[16], whp[16];
        LOAD_WROW(wip, eWih1)
        LOAD_WROW(whp, eWhh1)
        float bias1 = ebih1[lane] + ebhh1[lane];
        sB[r][0][lane] = 0.0f;
        WBAR();

        float h1 = 0.0f;
        for (int k = 0; k < ENC_CHUNKS; k++) {
            while (prod[r] < k + 1) __nanosleep(32);
            __threadfence_block();
            WBAR();
            const float* slot = (const float*)&ring[r][k & (NRING - 1)][0][0];
#pragma unroll
            for (int s = 0; s < CH; s++) {
                const int t = k * CH + s;
                const int cur = t & 1, nxt = cur ^ 1;
                const float d1 = dot32w(wip, &slot[s * HH], bias1);
                const float d2 = dot32w(whp, sB[r][cur], 0.0f);
                h1 = ftanh(d1 + d2);
                sB[r][nxt][lane] = h1;
                WBAR();
            }
            __threadfence_block();
            __syncwarp();
            if (lane == 0) cons[r] = k + 1;
        }
        const float hT1 = h1;

        // transition layer 1: t1[p] = tanh(bias1 + Wih1 . t0[p] + Whh1 . t1[p-1])
        LOAD_WROW(wip, tWih1)
        LOAD_WROW(whp, tWhh1)
        bias1 = tbih1[lane] + tbhh1[lane];
        sB[r][0][lane] = hT1;
        WBAR();

        float* tp = g_ts1 + (long)b * HH + lane;
        for (int k = 0; k < TRA_CHUNKS; k++) {
            const int gk = ENC_CHUNKS + k;
            while (prod[r] < gk + 1) __nanosleep(32);
            __threadfence_block();
            WBAR();
            const float* slot = (const float*)&ring[r][gk & (NRING - 1)][0][0];
#pragma unroll
            for (int s = 0; s < CH; s++) {
                const int p = k * CH + s;
                const int cur = p & 1, nxt = cur ^ 1;
                const float d1 = dot32w(wip, &slot[s * HH], bias1);
                const float d2 = dot32w(whp, sB[r][cur], 0.0f);
                h1 = ftanh(d1 + d2);
                tp[(long)p * ST] = h1;
                sB[r][nxt][lane] = h1;
                WBAR();
            }
            __threadfence_block();
            __syncwarp();
            if (lane == 0) cons[r] = gk + 1;
        }
    }
}

// ============================================================================
// Kernel 3: observation MLP (R8/R9-verified: 137us). 128-row tile,
// launch_bounds(256,2), fast gelu.
// ============================================================================
#define MLP_SMEM_FLOATS (4096 + 2304 + 4352 + 8192 + 128)

__global__ __launch_bounds__(256, 2) void k_mlp(const float* __restrict__ W1,
                                                const float* __restrict__ b1,
                                                const float* __restrict__ W2,
                                                const float* __restrict__ b2,
                                                float* __restrict__ out) {
    extern __shared__ __align__(16) float sm[];
    float* Xs  = sm;                  // [128][32]
    float* W1s = sm + 4096;           // [64][36]
    float* W2s = sm + 6400;           // [64][68]
    float* Gs  = sm + 10752;          // [128][64]
    float* b1s = sm + 18944;
    float* b2s = sm + 19008;

    const int tid = threadIdx.x;
    const int tx = tid & 15;          // col: e_j = tx + 16*j
    const int ty = tid >> 4;          // rows 8*ty .. 8*ty+7
    const int p0 = blockIdx.x * 16;
    const int b0 = blockIdx.y * 8;

    for (int i4 = tid; i4 < 1024; i4 += 256) {
        const int r = i4 >> 3, c4 = i4 & 7;
        const int bl = r >> 4, pl = r & 15;
        ((float4*)Xs)[i4] =
            *(const float4*)&g_ts1[((long)(p0 + pl) * BB + (b0 + bl)) * HH + 4 * c4];
    }
    for (int i4 = tid; i4 < 512; i4 += 256) {
        const int j = i4 >> 3, k4 = i4 & 7;
        ((float4*)W1s)[j * 9 + k4] = ((const float4*)W1)[i4];
    }
    for (int i4 = tid; i4 < 1024; i4 += 256) {
        const int e = i4 >> 4, j4 = i4 & 15;
        ((float4*)W2s)[e * 17 + j4] = ((const float4*)W2)[i4];
    }
    if (tid < 64) b1s[tid] = b1[tid];
    else if (tid < 128) b2s[tid - 64] = b2[tid - 64];
    __syncthreads();

    u64 acc[8][4];
#pragma unroll
    for (int i = 0; i < 8; i++)
#pragma unroll
        for (int j = 0; j < 4; j++) acc[i][j] = pk(b1s[tx + 16 * j], 0.0f);

#pragma unroll
    for (int k4 = 0; k4 < 8; k4++) {
        ulonglong2 wv[4];
#pragma unroll
        for (int j = 0; j < 4; j++)
            wv[j] = *(const ulonglong2*)&W1s[(tx + 16 * j) * 36 + 4 * k4];
#pragma unroll
        for (int i = 0; i < 8; i++) {
            ulonglong2 xv = *(const ulonglong2*)&Xs[(8 * ty + i) * 32 + 4 * k4];
#pragma unroll
            for (int j = 0; j < 4; j++) {
                acc[i][j] = fma2(xv.x, wv[j].x, acc[i][j]);
                acc[i][j] = fma2(xv.y, wv[j].y, acc[i][j]);
            }
        }
    }

#pragma unroll
    for (int i = 0; i < 8; i++) {
#pragma unroll
        for (int j = 0; j < 4; j++) {
            float2 uj = upk(acc[i][j]);
            Gs[(8 * ty + i) * 64 + tx + 16 * j] = gelu(uj.x + uj.y);
        }
    }
    __syncthreads();

#pragma unroll
    for (int i = 0; i < 8; i++)
#pragma unroll
        for (int j = 0; j < 4; j++) acc[i][j] = pk(b2s[tx + 16 * j], 0.0f);

#pragma unroll
    for (int k4 = 0; k4 < 16; k4++) {
        ulonglong2 wv[4];
#pragma unroll
        for (int j = 0; j < 4; j++)
            wv[j] = *(const ulonglong2*)&W2s[(tx + 16 * j) * 68 + 4 * k4];
#pragma unroll
        for (int i = 0; i < 8; i++) {
            ulonglong2 gv = *(const ulonglong2*)&Gs[(8 * ty + i) * 64 + 4 * k4];
#pragma unroll
            for (int j = 0; j < 4; j++) {
                acc[i][j] = fma2(gv.x, wv[j].x, acc[i][j]);
                acc[i][j] = fma2(gv.y, wv[j].y, acc[i][j]);
            }
        }
    }

    float y[8][4];
#pragma unroll
    for (int i = 0; i < 8; i++)
#pragma unroll
        for (int j = 0; j < 4; j++) {
            float2 uj = upk(acc[i][j]);
            y[i][j] = uj.x + uj.y;
        }

    const int bl = ty >> 1;
    const int plb = (ty & 1) * 8;
    float* ob = out + (long)(b0 + bl) * EE * PP + p0 + plb;
#pragma unroll
    for (int j = 0; j < 4; j++) {
        const int e = tx + 16 * j;
#pragma unroll
        for (int q = 0; q < 2; q++) {
            float4 v;
            v.x = y[4 * q + 0][j]; v.y = y[4 * q + 1][j];
            v.z = y[4 * q + 2][j]; v.w = y[4 * q + 3][j];
            *(float4*)&ob[(long)e * PP + 4 * q] = v;
        }
    }
}

// ============================================================================
extern "C" void kernel_launch(void* const* d_in, const int* in_sizes, int n_in,
                              void* d_out, int out_size) {
    (void)in_sizes; (void)n_in; (void)out_size;
    const float* x      = (const float*)d_in[0];
    const float* e_Wih0 = (const float*)d_in[1];
    const float* e_Whh0 = (const float*)d_in[2];
    const float* e_bih0 = (const float*)d_in[3];
    const float* e_bhh0 = (const float*)d_in[4];
    const float* e_Wih1 = (const float*)d_in[5];
    const float* e_Whh1 = (const float*)d_in[6];
    const float* e_bih1 = (const float*)d_in[7];
    const float* e_bhh1 = (const float*)d_in[8];
    // d_in[9] = t_Wih0: unused (transition input is zeros)
    const float* t_Whh0 = (const float*)d_in[10];
    const float* t_bih0 = (const float*)d_in[11];
    const float* t_bhh0 = (const float*)d_in[12];
    const float* t_Wih1 = (const float*)d_in[13];
    const float* t_Whh1 = (const float*)d_in[14];
    const float* t_bih1 = (const float*)d_in[15];
    const float* t_bhh1 = (const float*)d_in[16];
    const float* o_W1   = (const float*)d_in[17];
    const float* o_b1   = (const float*)d_in[18];
    const float* o_W2   = (const float*)d_in[19];
    const float* o_b2   = (const float*)d_in[20];
    float* out = (float*)d_out;

    cudaFuncSetAttribute(k_mlp, cudaFuncAttributeMaxDynamicSharedMemorySize,
                         MLP_SMEM_FLOATS * 4);

    k_z0<<<(BB * TT) / 64, 256>>>(x, e_Wih0, e_bih0, e_bhh0);
    k_scan2<<<BB / 4, 256>>>(e_Whh0, e_Wih1, e_Whh1, e_bih1, e_bhh1,
                             t_Whh0, t_bih0, t_bhh0, t_Wih1, t_Whh1,
                             t_bih1, t_bhh1);
    dim3 g(PP / 16, BB / 8);
    k_mlp<<<g, 256, MLP_SMEM_FLOATS * 4>>>(o_W1, o_b1, o_W2, o_b2, out);
}